// round 7
// baseline (speedup 1.0000x reference)
#include <cuda_runtime.h>
#include <cstdint>

// Problem constants (match reference)
#define SCR_W 1280
#define SCR_H 720
#define NBH   45
#define N_POINTS 32768

// ---------------------------------------------------------------------------
// Scatter: one thread per point; compute covered tile rectangle and store
// 1.0f into the float32 mask. Output layout: out[t * N + i], t = xi*NBH + yi.
// ---------------------------------------------------------------------------
__global__ void scatter_kernel(const float* __restrict__ pos2d,
                               const float* __restrict__ radius,
                               float* __restrict__ out, int n) {
    int i = blockIdx.x * blockDim.x + threadIdx.x;
    if (i >= n) return;

    float2 p = reinterpret_cast<const float2*>(pos2d)[i];
    float r = radius[i];

    // clip(v, 0, W/H) then truncate to int32 (values >= 0 -> floor)
    int xmin = (int)fminf(fmaxf(p.x - r, 0.0f), (float)SCR_W);
    int xmax = (int)fminf(fmaxf(p.x + r, 0.0f), (float)SCR_W);
    int ymin = (int)fminf(fmaxf(p.y - r, 0.0f), (float)SCR_H);
    int ymax = (int)fminf(fmaxf(p.y + r, 0.0f), (float)SCR_H);

    if (xmax <= xmin || ymax <= ymin) return;

    // W and H are multiples of 16, so the per-tile right/bottom clamps are
    // no-ops and tile xi overlaps iff xi*16 < xmax && (xi+1)*16 > xmin:
    //   xi in [xmin>>4, (xmax-1)>>4]   (xmax >= 1 here), same for y.
    int xlo = xmin >> 4;
    int xhi = (xmax - 1) >> 4;
    int ylo = ymin >> 4;
    int yhi = (ymax - 1) >> 4;

    for (int xi = xlo; xi <= xhi; ++xi) {
        size_t base = ((size_t)(xi * NBH + ylo)) * (size_t)N_POINTS + (size_t)i;
        #pragma unroll 1
        for (int yi = ylo; yi <= yhi; ++yi) {
            out[base] = 1.0f;
            base += (size_t)N_POINTS;   // next tile in y
        }
    }
}

extern "C" void kernel_launch(void* const* d_in, const int* in_sizes, int n_in,
                              void* d_out, int out_size) {
    const float* pos2d  = (const float*)d_in[0];
    const float* radius = (const float*)d_in[1];
    float* out = (float*)d_out;

    int n_points = in_sizes[1];   // radius element count == N

    // Zero-fill the full float32 output (graph-capturable async memset).
    cudaMemsetAsync(d_out, 0, (size_t)out_size * sizeof(float));

    // Scatter the true entries.
    int threads = 256;
    int blocks = (n_points + threads - 1) / threads;
    scatter_kernel<<<blocks, threads>>>(pos2d, radius, out, n_points);
}

// round 10
// speedup vs baseline: 1.0153x; 1.0153x over previous
#include <cuda_runtime.h>
#include <cstdint>

// Problem constants (match reference)
#define SCR_W 1280
#define SCR_H 720
#define NBH   45
#define N_POINTS 32768

// ---------------------------------------------------------------------------
// Kernel 1: streaming zero-fill. Each thread issues 4 coalesced STG.128
// (uint4) stores. Pure HBM-store-bound.
// ---------------------------------------------------------------------------
__global__ void fill_kernel(uint4* __restrict__ out, int n_vec) {
    // block covers 1024 consecutive uint4s in 4 coalesced waves
    int base = blockIdx.x * (blockDim.x * 4) + threadIdx.x;
    const uint4 z = make_uint4(0u, 0u, 0u, 0u);
    #pragma unroll
    for (int k = 0; k < 4; ++k) {
        int idx = base + k * blockDim.x;
        if (idx < n_vec) out[idx] = z;
    }
}

// ---------------------------------------------------------------------------
// Kernel 2: scatter. 4 threads per point; thread slot s handles tile columns
// xi = xlo + s, xlo + s + 4, ... (rect width <= 5 for r <= 31, so at most
// 2 iterations, usually <= 1). Each writes 1.0f down its y-run.
// ---------------------------------------------------------------------------
__global__ void scatter_kernel(const float* __restrict__ pos2d,
                               const float* __restrict__ radius,
                               float* __restrict__ out, int n) {
    int t = blockIdx.x * blockDim.x + threadIdx.x;
    int i = t >> 2;        // point index
    int s = t & 3;         // xi slot
    if (i >= n) return;

    float2 p = reinterpret_cast<const float2*>(pos2d)[i];
    float r = radius[i];

    // clip(v, 0, W/H) then truncate to int32 (values >= 0 -> floor)
    int xmin = (int)fminf(fmaxf(p.x - r, 0.0f), (float)SCR_W);
    int xmax = (int)fminf(fmaxf(p.x + r, 0.0f), (float)SCR_W);
    int ymin = (int)fminf(fmaxf(p.y - r, 0.0f), (float)SCR_H);
    int ymax = (int)fminf(fmaxf(p.y + r, 0.0f), (float)SCR_H);

    if (xmax <= xmin || ymax <= ymin) return;

    // W, H multiples of 16 -> tile xi overlaps iff xi in [xmin>>4, (xmax-1)>>4]
    int xlo = xmin >> 4;
    int xhi = (xmax - 1) >> 4;
    int ylo = ymin >> 4;
    int yhi = (ymax - 1) >> 4;

    for (int xi = xlo + s; xi <= xhi; xi += 4) {
        size_t base = ((size_t)(xi * NBH + ylo)) * (size_t)N_POINTS + (size_t)i;
        #pragma unroll 1
        for (int yi = ylo; yi <= yhi; ++yi) {
            out[base] = 1.0f;
            base += (size_t)N_POINTS;   // next tile in y
        }
    }
}

extern "C" void kernel_launch(void* const* d_in, const int* in_sizes, int n_in,
                              void* d_out, int out_size) {
    const float* pos2d  = (const float*)d_in[0];
    const float* radius = (const float*)d_in[1];
    float* out = (float*)d_out;

    int n_points = in_sizes[1];   // radius element count == N

    // --- zero fill (custom streaming kernel) ---
    size_t total_bytes = (size_t)out_size * sizeof(float);
    int n_vec = (int)(total_bytes / 16);          // uint4 count (472MB -> 29.49M)
    {
        int threads = 256;
        int per_block = threads * 4;
        int blocks = (n_vec + per_block - 1) / per_block;
        fill_kernel<<<blocks, threads>>>((uint4*)out, n_vec);
        // tail bytes: out_size*4 is a multiple of 16 here (32768*4 per tile row)
    }

    // --- scatter (4 threads per point) ---
    {
        int threads = 256;
        int total = n_points * 4;
        int blocks = (total + threads - 1) / threads;
        scatter_kernel<<<blocks, threads>>>(pos2d, radius, out, n_points);
    }
}